// round 3
// baseline (speedup 1.0000x reference)
#include <cuda_runtime.h>
#include <cuda_bf16.h>

#define G_MAX 128
#define BLOCK 256

// out_labels / out_boxes may be null depending on detected output layout.
__global__ __launch_bounds__(BLOCK)
void roi_match_kernel(const float4* __restrict__ props,
                      const float4* __restrict__ gt,
                      const int*    __restrict__ gtl32,   // gt labels, i32 or i64 (auto-detect)
                      float*        __restrict__ out_labels,
                      float4*       __restrict__ out_boxes,
                      int N, int G)
{
    __shared__ float4 s_gt[G_MAX];
    __shared__ float  s_area[G_MAX];
    __shared__ float  s_lab[G_MAX];

    const int t = threadIdx.x;
    if (t < G) {
        float4 b = gt[t];
        s_gt[t]   = b;
        s_area[t] = __fmul_rn(__fsub_rn(b.z, b.x), __fsub_rn(b.w, b.y));
        // int64 detection: labels are >= 1, so if stored as little-endian i64,
        // word index 1 (high word of element 0) is 0; if i32, it's label[1] >= 1.
        int is64 = (gtl32[1] == 0) ? 1 : 0;
        s_lab[t] = (float)gtl32[is64 ? (2 * t) : t];
    }
    __syncthreads();

    const int n = blockIdx.x * BLOCK + t;
    if (n >= N) return;

    const float4 p = props[n];
    const float parea = __fmul_rn(__fsub_rn(p.z, p.x), __fsub_rn(p.w, p.y));

    // g = 0 initializes the running best (argmax keeps first max under strict >)
    float bestI, bestU;
    int bestIdx = 0;
    {
        float4 gb = s_gt[0];
        float x1 = fmaxf(gb.x, p.x);
        float y1 = fmaxf(gb.y, p.y);
        float x2 = fminf(gb.z, p.z);
        float y2 = fminf(gb.w, p.w);
        float dx = fmaxf(__fsub_rn(x2, x1), 0.0f);
        float dy = fmaxf(__fsub_rn(y2, y1), 0.0f);
        bestI = __fmul_rn(dx, dy);
        bestU = __fsub_rn(__fadd_rn(s_area[0], parea), bestI);
    }

    #pragma unroll 8
    for (int g = 1; g < G; ++g) {
        float4 gb = s_gt[g];
        float x1 = fmaxf(gb.x, p.x);
        float y1 = fmaxf(gb.y, p.y);
        float x2 = fminf(gb.z, p.z);
        float y2 = fminf(gb.w, p.w);
        float dx = fmaxf(__fsub_rn(x2, x1), 0.0f);
        float dy = fmaxf(__fsub_rn(y2, y1), 0.0f);
        float inter = __fmul_rn(dx, dy);
        float uni   = __fsub_rn(__fadd_rn(s_area[g], parea), inter);
        // inter/uni > bestI/bestU  <=>  inter*bestU > bestI*uni  (uni, bestU > 0)
        // Division-free argmax; exact ties (e.g. both inter==0) keep earlier index,
        // matching jnp.argmax first-max semantics.
        bool take = (inter * bestU) > (bestI * uni);
        bestI   = take ? inter : bestI;
        bestU   = take ? uni   : bestU;
        bestIdx = take ? g     : bestIdx;
    }

    // Single IEEE-rounded division: bitwise identical to the reference's fp32
    // quotient for the winning (inter, union) pair -> threshold tests match.
    float iou = __fdiv_rn(bestI, bestU);
    float lab = s_lab[bestIdx];
    if (iou < 0.5f) lab = (iou >= 0.1f) ? 0.0f : -1.0f;

    if (out_labels) out_labels[n] = lab;
    if (out_boxes)  out_boxes[n]  = s_gt[bestIdx];
}

extern "C" void kernel_launch(void* const* d_in, const int* in_sizes, int n_in,
                              void* d_out, int out_size)
{
    const float4* props = (const float4*)d_in[0];
    const float4* gt    = (const float4*)d_in[1];
    const int*    gtl   = (const int*)d_in[2];

    const int N = in_sizes[0] / 4;
    const int G = in_sizes[1] / 4;

    float*  out       = (float*)d_out;
    float*  out_label = nullptr;
    float4* out_boxes = nullptr;

    if (out_size == 5 * N) {            // [labels (N) ; boxes (4N)] as f32
        out_label = out;
        out_boxes = (float4*)(out + N); // byte offset 4N, 16B-aligned for N%4==0
    } else if (out_size == 4 * N) {     // boxes only
        out_boxes = (float4*)out;
    } else {                            // labels only
        out_label = out;
    }

    const int grid = (N + BLOCK - 1) / BLOCK;
    roi_match_kernel<<<grid, BLOCK>>>(props, gt, gtl, out_label, out_boxes, N, G);
}